// round 12
// baseline (speedup 1.0000x reference)
#include <cuda_runtime.h>
#include <cuda_fp16.h>
#include <cstdint>

// CrossInferenceBlock via fp16 mma.sync (HMMA), all stages 1-pass, merged launches:
//  L1 prep: batch->fp16, a_w/b_w/g_w transposed->fp16          (one kernel)
//  L2 tp   = batch @ [a_w|b_w] + bias  (65536 x 512)
//  L3 merged: attn[t] = theta[t]@phi[t]^T  (blocks 0..1023)
//           + featsT[t][f][s] = (batch@g_w + g_b)^T (blocks 1024..5119)
//  L4 out[t] = (attn[t] @ feats[t]) / 512  fp32
// GEMM: C[m][n] = sum_k A[m,k]*B[n,k], all K-major fp16.

#define TT 256
#define SS 256
#define FF 1024
#define AA 256

// ------------------------------- static scratch
__device__ __align__(16) __half g_batchH[67108864];  // [65536][1024]
__device__ __align__(16) __half g_wTH[524288];       // [512][1024] = aT|bT
__device__ __align__(16) __half g_gTH[1048576];      // g_w^T
__device__ __align__(16) __half g_tpH[33554432];     // [65536][512] theta|phi
__device__ __align__(16) __half g_attnH[16777216];   // [65536][256]
__device__ __align__(16) __half g_featsTH[67108864]; // [256][1024][256]

// ------------------------------- helpers
__device__ __forceinline__ uint32_t smem_u32(const void* p) {
    uint32_t a;
    asm("{ .reg .u64 t; cvta.to.shared.u64 t, %1; cvt.u32.u64 %0, t; }"
        : "=r"(a) : "l"(p));
    return a;
}
__device__ __forceinline__ void cpasync16(uint32_t s, const void* g) {
    asm volatile("cp.async.cg.shared.global [%0], [%1], 16;" :: "r"(s), "l"(g));
}
__device__ __forceinline__ void cp_commit() { asm volatile("cp.async.commit_group;"); }
template <int N>
__device__ __forceinline__ void cp_wait() {
    asm volatile("cp.async.wait_group %0;" :: "n"(N));
}
__device__ __forceinline__ uint4 ldsm4(uint32_t a) {
    uint4 r;
    asm volatile("ldmatrix.sync.aligned.m8n8.x4.shared.b16 {%0,%1,%2,%3}, [%4];"
                 : "=r"(r.x), "=r"(r.y), "=r"(r.z), "=r"(r.w) : "r"(a));
    return r;
}
__device__ __forceinline__ void mma_f16(float* c, const uint4& a,
                                        uint32_t b0, uint32_t b1) {
    asm volatile(
        "mma.sync.aligned.m16n8k16.row.col.f32.f16.f16.f32 "
        "{%0,%1,%2,%3},{%4,%5,%6,%7},{%8,%9},{%0,%1,%2,%3};"
        : "+f"(c[0]), "+f"(c[1]), "+f"(c[2]), "+f"(c[3])
        : "r"(a.x), "r"(a.y), "r"(a.z), "r"(a.w), "r"(b0), "r"(b1));
}

// ------------------------------- prep kernel (cvt + 3 transposes, merged)
__global__ void __launch_bounds__(256) prep_kernel(
    const float* __restrict__ batch, __half* __restrict__ batchH,
    const float* __restrict__ a_w, const float* __restrict__ b_w,
    const float* __restrict__ g_w,
    __half* __restrict__ wTH, __half* __restrict__ gTH)
{
    __shared__ float t[32][33];
    const int b = blockIdx.x;
    const int tid = threadIdx.x;

    if (b < 32768) {
        // cvt batch -> batchH (fp32 -> fp16), 8 elems/thread
        long i = ((long)b * 256 + tid) * 8;
        float4 v0 = *(const float4*)(batch + i);
        float4 v1 = *(const float4*)(batch + i + 4);
        __half2 a = __floats2half2_rn(v0.x, v0.y);
        __half2 bb = __floats2half2_rn(v0.z, v0.w);
        __half2 c = __floats2half2_rn(v1.x, v1.y);
        __half2 d = __floats2half2_rn(v1.z, v1.w);
        *(uint4*)(batchH + i) = make_uint4(*(uint32_t*)&a, *(uint32_t*)&bb,
                                           *(uint32_t*)&c, *(uint32_t*)&d);
        return;
    }
    // transpose branches
    const float* in;
    __half* oh;
    int R, C, bx, by;
    if (b < 33024) {        // a_w (1024x256) -> wTH[0]
        int id = b - 32768; in = a_w; oh = wTH; R = FF; C = AA;
        bx = id & 7; by = id >> 3;
    } else if (b < 33280) { // b_w -> wTH + 256*1024
        int id = b - 33024; in = b_w; oh = wTH + 256 * 1024; R = FF; C = AA;
        bx = id & 7; by = id >> 3;
    } else {                // g_w (1024x1024) -> gTH
        int id = b - 33280; in = g_w; oh = gTH; R = FF; C = FF;
        bx = id & 31; by = id >> 5;
    }
    const int c0 = bx * 32, r0 = by * 32;
    const int x = tid & 31, y = tid >> 5;   // 32 x 8
#pragma unroll
    for (int i = 0; i < 32; i += 8)
        t[y + i][x] = in[(long)(r0 + y + i) * C + c0 + x];
    __syncthreads();
#pragma unroll
    for (int i = 0; i < 32; i += 8)
        oh[(long)(c0 + y + i) * R + r0 + x] = __float2half_rn(t[x][y + i]);
}

// ------------------------------- GEMM body: BM=128 BN=128 BK=64, 3-stage cp.async
static constexpr int TILE = 16384;  // 128 x 64 fp16
static constexpr int OFF_AH = 0;
static constexpr int OFF_BH = TILE;

// BMODE: 0 none, 1 col-bias (bias n<256 / bias2 n>=256), 2 row-bias (bias[m])
// OUTM : 0 = fp16, 2 = fp32
template <int BMODE, int OUTM>
__device__ __forceinline__ void gemm_body(
    int bx, int by, long z,
    const __half* __restrict__ Ah, const __half* __restrict__ Bh,
    const float* __restrict__ bias, const float* __restrict__ bias2,
    __half* __restrict__ Ch, float* __restrict__ Cf,
    int N, int K, int lda, int ldb, int ldc, float scale,
    long sA, long sB, long sC, char* smem)
{
    constexpr int STAGE = 2 * TILE;
    const uint32_t sbase = smem_u32(smem);
    const int tid = threadIdx.x;
    const int wid = tid >> 5, lane = tid & 31;
    const int block_row = by * 128;
    const int block_col = bx * 128;

    const __half* Az_h = Ah + z * sA + (long)block_row * lda;
    const __half* Bz_h = Bh + z * sB + (long)block_col * ldb;

    int c_row[4]; int c_co[4]; uint32_t c_so[4];
#pragma unroll
    for (int i = 0; i < 4; i++) {
        int q = tid + i * 256;
        int r = q >> 3, u = q & 7;
        c_row[i] = r;
        c_co[i] = u * 8;
        c_so[i] = (uint32_t)(r * 128 + ((u ^ (r & 7)) << 4));
    }

    auto load_stage = [&](int buf, int k0) {
        uint32_t sb = sbase + buf * STAGE;
#pragma unroll
        for (int i = 0; i < 4; i++) {
            long ga = (long)c_row[i] * lda + k0 + c_co[i];
            long gb = (long)c_row[i] * ldb + k0 + c_co[i];
            cpasync16(sb + OFF_AH + c_so[i], Az_h + ga);
            cpasync16(sb + OFF_BH + c_so[i], Bz_h + gb);
        }
    };

    const int wm = wid & 1, wn = wid >> 1;
    const int arow = wm * 64 + (lane & 15);
    const uint32_t asel = ((lane >> 4) & 1) * 16;
    const uint32_t axr = (uint32_t)((arow & 7) << 4);
    const int brow = wn * 32 + (lane & 7) + ((lane & 16) ? 8 : 0);
    const uint32_t bsel = (lane & 8) ? 16u : 0u;
    const uint32_t bxr = (uint32_t)((brow & 7) << 4);

    float acc[4][4][4];
#pragma unroll
    for (int a = 0; a < 4; a++)
#pragma unroll
        for (int b = 0; b < 4; b++)
#pragma unroll
            for (int c = 0; c < 4; c++) acc[a][b][c] = 0.0f;

    const int NT = K >> 6;
    load_stage(0, 0);
    cp_commit();
    if (NT > 1) load_stage(1, 64);
    cp_commit();

    int buf = 0;
    for (int it = 0; it < NT; it++) {
        cp_wait<1>();
        __syncthreads();
        if (it + 2 < NT) load_stage((it + 2) % 3, (it + 2) << 6);
        cp_commit();

        const uint32_t sb = sbase + buf * STAGE;
#pragma unroll
        for (int kk = 0; kk < 4; kk++) {
            uint4 ah[4], bhf[2];
#pragma unroll
            for (int mi = 0; mi < 4; mi++) {
                uint32_t ro = (uint32_t)((arow + mi * 16) * 128) +
                              (((uint32_t)(kk * 32) + asel) ^ axr);
                ah[mi] = ldsm4(sb + OFF_AH + ro);
            }
#pragma unroll
            for (int pi = 0; pi < 2; pi++) {
                uint32_t ro = (uint32_t)((brow + pi * 16) * 128) +
                              (((uint32_t)(kk * 32) + bsel) ^ bxr);
                bhf[pi] = ldsm4(sb + OFF_BH + ro);
            }
#pragma unroll
            for (int mi = 0; mi < 4; mi++) {
#pragma unroll
                for (int ni = 0; ni < 4; ni++) {
                    const int pi = ni >> 1;
                    const bool up = ni & 1;
                    uint32_t bh0 = up ? bhf[pi].z : bhf[pi].x;
                    uint32_t bh1 = up ? bhf[pi].w : bhf[pi].y;
                    mma_f16(acc[mi][ni], ah[mi], bh0, bh1);
                }
            }
        }
        buf = (buf + 1) % 3;
    }

    const int grow0 = block_row + wm * 64 + (lane >> 2);
    const int gcol0 = block_col + wn * 32 + (lane & 3) * 2;
#pragma unroll
    for (int mi = 0; mi < 4; mi++) {
#pragma unroll
        for (int ni = 0; ni < 4; ni++) {
            float v0 = acc[mi][ni][0], v1 = acc[mi][ni][1];
            float v2 = acc[mi][ni][2], v3 = acc[mi][ni][3];
            const int r0 = grow0 + mi * 16, r1 = r0 + 8;
            const int cc = gcol0 + ni * 8;
            if (BMODE == 1) {
                float b0 = (cc < 256) ? bias[cc] : bias2[cc - 256];
                float b1 = (cc + 1 < 256) ? bias[cc + 1] : bias2[cc + 1 - 256];
                v0 += b0; v1 += b1; v2 += b0; v3 += b1;
            }
            if (BMODE == 2) {
                float ba = bias[r0], bb = bias[r1];
                v0 += ba; v1 += ba; v2 += bb; v3 += bb;
            }
            v0 *= scale; v1 *= scale; v2 *= scale; v3 *= scale;
            const long o0 = z * sC + (long)r0 * ldc + cc;
            const long o1 = z * sC + (long)r1 * ldc + cc;
            if (OUTM == 0) {
                __half2 p0 = __floats2half2_rn(v0, v1);
                __half2 p1 = __floats2half2_rn(v2, v3);
                *(uint32_t*)(Ch + o0) = *(uint32_t*)&p0;
                *(uint32_t*)(Ch + o1) = *(uint32_t*)&p1;
            } else {
                *(float2*)(Cf + o0) = make_float2(v0, v1);
                *(float2*)(Cf + o1) = make_float2(v2, v3);
            }
        }
    }
}

// standalone GEMM kernel (tp, out)
template <int BMODE, int OUTM>
__global__ void __launch_bounds__(256, 2) gemm_hmma(
    const __half* __restrict__ Ah, const __half* __restrict__ Bh,
    const float* __restrict__ bias, const float* __restrict__ bias2,
    __half* __restrict__ Ch, float* __restrict__ Cf,
    int N, int K, int lda, int ldb, int ldc, float scale,
    long sA, long sB, long sC)
{
    extern __shared__ __align__(1024) char smem[];
    gemm_body<BMODE, OUTM>(blockIdx.x, blockIdx.y, blockIdx.z,
                           Ah, Bh, bias, bias2, Ch, Cf,
                           N, K, lda, ldb, ldc, scale, sA, sB, sC, smem);
}

// merged attn + featsT kernel: blocks [0,1024) attn, [1024,5120) featsT
__global__ void __launch_bounds__(256, 2) attn_feats_kernel(
    const __half* __restrict__ tpH, __half* __restrict__ attnH,
    const __half* __restrict__ gTH, const __half* __restrict__ batchH,
    const float* __restrict__ g_b, __half* __restrict__ featsTH)
{
    extern __shared__ __align__(1024) char smem[];
    const int bid = blockIdx.x;
    if (bid < 1024) {
        // attn[t] = theta[t] @ phi[t]^T : M=N=256, K=256
        int x = bid & 1, y = (bid >> 1) & 1;
        long z = bid >> 2;
        gemm_body<0, 0>(x, y, z, tpH, tpH + 256, nullptr, nullptr,
                        attnH, nullptr,
                        256, 256, 512, 512, 256, 1.0f,
                        131072, 131072, 65536, smem);
    } else {
        // featsT[t][f][s]: M=1024(f), N=256(s), K=1024
        int id = bid - 1024;
        int x = id & 1, y = (id >> 1) & 7;
        long z = id >> 4;
        gemm_body<2, 0>(x, y, z, gTH, batchH, g_b, nullptr,
                        featsTH, nullptr,
                        256, 1024, 1024, 1024, 256, 1.0f,
                        0, (long)256 * 1024, (long)1024 * 256, smem);
    }
}

static constexpr int SMEMB1 = 3 * 2 * TILE;  //  96 KB

// ------------------------------- launcher
extern "C" void kernel_launch(void* const* d_in, const int* in_sizes, int n_in,
                              void* d_out, int out_size)
{
    const float* batch = (const float*)d_in[0];
    const float* a_w   = (const float*)d_in[1];
    const float* a_b   = (const float*)d_in[2];
    const float* b_w   = (const float*)d_in[3];
    const float* b_b   = (const float*)d_in[4];
    const float* g_w   = (const float*)d_in[5];
    const float* g_b   = (const float*)d_in[6];
    float* out = (float*)d_out;

    void* p;
#define SYMH(v, s) cudaGetSymbolAddress(&p, s); __half* v = (__half*)p
    SYMH(batchH, g_batchH);
    SYMH(wTH, g_wTH);
    SYMH(gTH, g_gTH);
    SYMH(tpH, g_tpH);
    SYMH(attnH, g_attnH);
    SYMH(featsTH, g_featsTH);
#undef SYMH

    static bool attr_done = false;
    if (!attr_done) {
        cudaFuncSetAttribute(gemm_hmma<1, 0>,
                             cudaFuncAttributeMaxDynamicSharedMemorySize, SMEMB1);
        cudaFuncSetAttribute(gemm_hmma<0, 2>,
                             cudaFuncAttributeMaxDynamicSharedMemorySize, SMEMB1);
        cudaFuncSetAttribute(attn_feats_kernel,
                             cudaFuncAttributeMaxDynamicSharedMemorySize, SMEMB1);
        attr_done = true;
    }

    // L1: prep (cvt + 3 transposes) — 32768 + 256 + 256 + 1024 = 34304 blocks
    prep_kernel<<<34304, 256>>>(batch, batchH, a_w, b_w, g_w, wTH, gTH);

    // L2: tp = batch @ [a_w|b_w] + bias : M=65536, N=512, K=1024
    gemm_hmma<1, 0><<<dim3(4, 512, 1), 256, SMEMB1>>>(
        batchH, wTH, a_b, b_b, tpH, nullptr,
        512, 1024, 1024, 1024, 512, 1.0f, 0, 0, 0);

    // L3: attn (1024 blocks) + featsT (4096 blocks), merged
    attn_feats_kernel<<<5120, 256, SMEMB1>>>(
        tpH, attnH, gTH, batchH, g_b, featsTH);

    // L4: out[t] = (attn[t] @ feats[t]) / 512 : M=256, N=1024, K=256 (fp32)
    gemm_hmma<0, 2><<<dim3(8, 2, 256), 256, SMEMB1>>>(
        attnH, featsTH, nullptr, nullptr, nullptr, out,
        1024, 256, 256, 256, 1024, 1.0f / (float)(SS + TT),
        65536, (long)1024 * 256, (long)256 * 1024);
}

// round 13
// speedup vs baseline: 1.0850x; 1.0850x over previous
#include <cuda_runtime.h>
#include <cuda_fp16.h>
#include <cstdint>

// CrossInferenceBlock via fp16 mma.sync (HMMA), all stages 1-pass:
//  tp    = batch @ [a_w|b_w] + bias   (65536 x 512)
//  featsT[t][f][s] = (batch @ g_w + g_b)^T per t
//  attn[t] = theta[t] @ phi[t]^T      (256 x 256)
//  out[t]  = (attn[t] @ feats[t])/512  fp32, 2 t-values per CTA, .cs stores
// GEMM: C[m][n] = sum_k A[m,k]*B[n,k], all K-major fp16.

#define TT 256
#define SS 256
#define FF 1024
#define AA 256

// ------------------------------- static scratch
__device__ __align__(16) __half g_batchH[67108864];  // [65536][1024]
__device__ __align__(16) __half g_wTH[524288];       // [512][1024] = aT|bT
__device__ __align__(16) __half g_gTH[1048576];      // g_w^T
__device__ __align__(16) __half g_tpH[33554432];     // [65536][512] theta|phi
__device__ __align__(16) __half g_attnH[16777216];   // [65536][256]
__device__ __align__(16) __half g_featsTH[67108864]; // [256][1024][256]

// ------------------------------- helpers
__device__ __forceinline__ uint32_t smem_u32(const void* p) {
    uint32_t a;
    asm("{ .reg .u64 t; cvta.to.shared.u64 t, %1; cvt.u32.u64 %0, t; }"
        : "=r"(a) : "l"(p));
    return a;
}
__device__ __forceinline__ void cpasync16(uint32_t s, const void* g) {
    asm volatile("cp.async.cg.shared.global [%0], [%1], 16;" :: "r"(s), "l"(g));
}
__device__ __forceinline__ void cp_commit() { asm volatile("cp.async.commit_group;"); }
template <int N>
__device__ __forceinline__ void cp_wait() {
    asm volatile("cp.async.wait_group %0;" :: "n"(N));
}
__device__ __forceinline__ uint4 ldsm4(uint32_t a) {
    uint4 r;
    asm volatile("ldmatrix.sync.aligned.m8n8.x4.shared.b16 {%0,%1,%2,%3}, [%4];"
                 : "=r"(r.x), "=r"(r.y), "=r"(r.z), "=r"(r.w) : "r"(a));
    return r;
}
__device__ __forceinline__ void mma_f16(float* c, const uint4& a,
                                        uint32_t b0, uint32_t b1) {
    asm volatile(
        "mma.sync.aligned.m16n8k16.row.col.f32.f16.f16.f32 "
        "{%0,%1,%2,%3},{%4,%5,%6,%7},{%8,%9},{%0,%1,%2,%3};"
        : "+f"(c[0]), "+f"(c[1]), "+f"(c[2]), "+f"(c[3])
        : "r"(a.x), "r"(a.y), "r"(a.z), "r"(a.w), "r"(b0), "r"(b1));
}
__device__ __forceinline__ void stg_cs_f2(float* p, float v0, float v1) {
    asm volatile("st.global.cs.v2.f32 [%0], {%1, %2};"
                 :: "l"(p), "f"(v0), "f"(v1) : "memory");
}

// ------------------------------- converters
__global__ void cvt_kernel(const float* __restrict__ in, __half* __restrict__ oh,
                           long n) {
    long i = ((long)blockIdx.x * blockDim.x + threadIdx.x) * 8;
    if (i >= n) return;
    float4 v0 = *(const float4*)(in + i);
    float4 v1 = *(const float4*)(in + i + 4);
    __half2 a = __floats2half2_rn(v0.x, v0.y);
    __half2 b = __floats2half2_rn(v0.z, v0.w);
    __half2 c = __floats2half2_rn(v1.x, v1.y);
    __half2 d = __floats2half2_rn(v1.z, v1.w);
    *(uint4*)(oh + i) = make_uint4(*(uint32_t*)&a, *(uint32_t*)&b,
                                   *(uint32_t*)&c, *(uint32_t*)&d);
}

__global__ void transpose_cvt_kernel(const float* __restrict__ in,
                                     __half* __restrict__ oh, int R, int C) {
    __shared__ float t[32][33];
    int c0 = blockIdx.x * 32, r0 = blockIdx.y * 32;
    int x = threadIdx.x, y = threadIdx.y;  // 32 x 8
#pragma unroll
    for (int i = 0; i < 32; i += 8)
        t[y + i][x] = in[(long)(r0 + y + i) * C + c0 + x];
    __syncthreads();
#pragma unroll
    for (int i = 0; i < 32; i += 8)
        oh[(long)(c0 + y + i) * R + r0 + x] = __float2half_rn(t[x][y + i]);
}

// ------------------------------- GEMM: BM=128 BN=128 BK=64, 3-stage cp.async
static constexpr int TILE = 16384;  // 128 x 64 fp16
static constexpr int OFF_AH = 0;
static constexpr int OFF_BH = TILE;

// BMODE: 0 none, 1 col-bias (bias n<256 / bias2 n>=256), 2 row-bias (bias[m])
// OUTM : 0 = fp16, 2 = fp32
template <int BMODE, int OUTM>
__global__ void __launch_bounds__(256, 2) gemm_hmma(
    const __half* __restrict__ Ah, const __half* __restrict__ Bh,
    const float* __restrict__ bias, const float* __restrict__ bias2,
    __half* __restrict__ Ch, float* __restrict__ Cf,
    int N, int K, int lda, int ldb, int ldc, float scale,
    long sA, long sB, long sC)
{
    constexpr int STAGE = 2 * TILE;
    extern __shared__ __align__(1024) char smem[];
    const uint32_t sbase = smem_u32(smem);
    const int tid = threadIdx.x;
    const int wid = tid >> 5, lane = tid & 31;
    const long z = blockIdx.z;
    const int block_row = blockIdx.y * 128;
    const int block_col = blockIdx.x * 128;

    const __half* Az_h = Ah + z * sA + (long)block_row * lda;
    const __half* Bz_h = Bh + z * sB + (long)block_col * ldb;

    int c_row[4]; int c_co[4]; uint32_t c_so[4];
#pragma unroll
    for (int i = 0; i < 4; i++) {
        int q = tid + i * 256;
        int r = q >> 3, u = q & 7;
        c_row[i] = r;
        c_co[i] = u * 8;
        c_so[i] = (uint32_t)(r * 128 + ((u ^ (r & 7)) << 4));
    }

    auto load_stage = [&](int buf, int k0) {
        uint32_t sb = sbase + buf * STAGE;
#pragma unroll
        for (int i = 0; i < 4; i++) {
            long ga = (long)c_row[i] * lda + k0 + c_co[i];
            long gb = (long)c_row[i] * ldb + k0 + c_co[i];
            cpasync16(sb + OFF_AH + c_so[i], Az_h + ga);
            cpasync16(sb + OFF_BH + c_so[i], Bz_h + gb);
        }
    };

    const int wm = wid & 1, wn = wid >> 1;
    const int arow = wm * 64 + (lane & 15);
    const uint32_t asel = ((lane >> 4) & 1) * 16;
    const uint32_t axr = (uint32_t)((arow & 7) << 4);
    const int brow = wn * 32 + (lane & 7) + ((lane & 16) ? 8 : 0);
    const uint32_t bsel = (lane & 8) ? 16u : 0u;
    const uint32_t bxr = (uint32_t)((brow & 7) << 4);

    float acc[4][4][4];
#pragma unroll
    for (int a = 0; a < 4; a++)
#pragma unroll
        for (int b = 0; b < 4; b++)
#pragma unroll
            for (int c = 0; c < 4; c++) acc[a][b][c] = 0.0f;

    const int NT = K >> 6;
    load_stage(0, 0);
    cp_commit();
    if (NT > 1) load_stage(1, 64);
    cp_commit();

    int buf = 0;
    for (int it = 0; it < NT; it++) {
        cp_wait<1>();
        __syncthreads();
        if (it + 2 < NT) load_stage((it + 2) % 3, (it + 2) << 6);
        cp_commit();

        const uint32_t sb = sbase + buf * STAGE;
#pragma unroll
        for (int kk = 0; kk < 4; kk++) {
            uint4 ah[4], bhf[2];
#pragma unroll
            for (int mi = 0; mi < 4; mi++) {
                uint32_t ro = (uint32_t)((arow + mi * 16) * 128) +
                              (((uint32_t)(kk * 32) + asel) ^ axr);
                ah[mi] = ldsm4(sb + OFF_AH + ro);
            }
#pragma unroll
            for (int pi = 0; pi < 2; pi++) {
                uint32_t ro = (uint32_t)((brow + pi * 16) * 128) +
                              (((uint32_t)(kk * 32) + bsel) ^ bxr);
                bhf[pi] = ldsm4(sb + OFF_BH + ro);
            }
#pragma unroll
            for (int mi = 0; mi < 4; mi++) {
#pragma unroll
                for (int ni = 0; ni < 4; ni++) {
                    const int pi = ni >> 1;
                    const bool up = ni & 1;
                    uint32_t bh0 = up ? bhf[pi].z : bhf[pi].x;
                    uint32_t bh1 = up ? bhf[pi].w : bhf[pi].y;
                    mma_f16(acc[mi][ni], ah[mi], bh0, bh1);
                }
            }
        }
        buf = (buf + 1) % 3;
    }

    const int grow0 = block_row + wm * 64 + (lane >> 2);
    const int gcol0 = block_col + wn * 32 + (lane & 3) * 2;
#pragma unroll
    for (int mi = 0; mi < 4; mi++) {
#pragma unroll
        for (int ni = 0; ni < 4; ni++) {
            float v0 = acc[mi][ni][0], v1 = acc[mi][ni][1];
            float v2 = acc[mi][ni][2], v3 = acc[mi][ni][3];
            const int r0 = grow0 + mi * 16, r1 = r0 + 8;
            const int cc = gcol0 + ni * 8;
            if (BMODE == 1) {
                float b0 = (cc < 256) ? bias[cc] : bias2[cc - 256];
                float b1 = (cc + 1 < 256) ? bias[cc + 1] : bias2[cc + 1 - 256];
                v0 += b0; v1 += b1; v2 += b0; v3 += b1;
            }
            if (BMODE == 2) {
                float ba = bias[r0], bb = bias[r1];
                v0 += ba; v1 += ba; v2 += bb; v3 += bb;
            }
            v0 *= scale; v1 *= scale; v2 *= scale; v3 *= scale;
            const long o0 = z * sC + (long)r0 * ldc + cc;
            const long o1 = z * sC + (long)r1 * ldc + cc;
            if (OUTM == 0) {
                __half2 p0 = __floats2half2_rn(v0, v1);
                __half2 p1 = __floats2half2_rn(v2, v3);
                *(uint32_t*)(Ch + o0) = *(uint32_t*)&p0;
                *(uint32_t*)(Ch + o1) = *(uint32_t*)&p1;
            } else {
                *(float2*)(Cf + o0) = make_float2(v0, v1);
                *(float2*)(Cf + o1) = make_float2(v2, v3);
            }
        }
    }
}

// ------------------------------- out kernel: 2 t-values per CTA, continuous pipe
// grid (8, 2, 128): x = nb (f-block), y = m-half, z -> t = 2z, 2z+1.
// 8 g-iters (ti*4 + kt), acc reset at g=0,4; epilogue at g=3,7. .cs stores.
__global__ void __launch_bounds__(256, 2) out_kernel(
    const __half* __restrict__ attnH, const __half* __restrict__ featsTH,
    float* __restrict__ out, float scale)
{
    extern __shared__ __align__(1024) char smem[];
    const uint32_t sbase = smem_u32(smem);
    const int tid = threadIdx.x;
    const int wid = tid >> 5, lane = tid & 31;
    const int nb = blockIdx.x, mh = blockIdx.y;
    const long z2 = (long)blockIdx.z * 2;

    int c_row[4]; int c_co[4]; uint32_t c_so[4];
#pragma unroll
    for (int i = 0; i < 4; i++) {
        int q = tid + i * 256;
        int r = q >> 3, u = q & 7;
        c_row[i] = r;
        c_co[i] = u * 8;
        c_so[i] = (uint32_t)(r * 128 + ((u ^ (r & 7)) << 4));
    }

    auto loadg = [&](int buf, int g) {   // g = ti*4 + kt
        uint32_t sb = sbase + buf * 2 * TILE;
        const long t = z2 + (g >> 2);
        const int kt = g & 3;
        const __half* Aa = attnH + (t * 256 + mh * 128) * 256;
        const __half* Bf = featsTH + t * 262144 + (long)nb * 128 * 256;
#pragma unroll
        for (int i = 0; i < 4; i++) {
            long ga = (long)c_row[i] * 256 + kt * 64 + c_co[i];
            cpasync16(sb + OFF_AH + c_so[i], Aa + ga);
            cpasync16(sb + OFF_BH + c_so[i], Bf + ga);
        }
    };

    const int wm = wid & 1, wn = wid >> 1;
    const int arow = wm * 64 + (lane & 15);
    const uint32_t asel = ((lane >> 4) & 1) * 16;
    const uint32_t axr = (uint32_t)((arow & 7) << 4);
    const int brow = wn * 32 + (lane & 7) + ((lane & 16) ? 8 : 0);
    const uint32_t bsel = (lane & 8) ? 16u : 0u;
    const uint32_t bxr = (uint32_t)((brow & 7) << 4);
    const int grow_l = wm * 64 + (lane >> 2);
    const int gcol_l = wn * 32 + (lane & 3) * 2;

    float acc[4][4][4];

    loadg(0, 0);
    cp_commit();
    loadg(1, 1);
    cp_commit();

    int buf = 0;
    for (int g = 0; g < 8; g++) {
        if ((g & 3) == 0) {
#pragma unroll
            for (int a = 0; a < 4; a++)
#pragma unroll
                for (int b = 0; b < 4; b++)
#pragma unroll
                    for (int c = 0; c < 4; c++) acc[a][b][c] = 0.0f;
        }
        cp_wait<1>();
        __syncthreads();
        if (g + 2 < 8) loadg((g + 2) % 3, g + 2);
        cp_commit();

        const uint32_t sb = sbase + buf * 2 * TILE;
#pragma unroll
        for (int kk = 0; kk < 4; kk++) {
            uint4 ah[4], bhf[2];
#pragma unroll
            for (int mi = 0; mi < 4; mi++) {
                uint32_t ro = (uint32_t)((arow + mi * 16) * 128) +
                              (((uint32_t)(kk * 32) + asel) ^ axr);
                ah[mi] = ldsm4(sb + OFF_AH + ro);
            }
#pragma unroll
            for (int pi = 0; pi < 2; pi++) {
                uint32_t ro = (uint32_t)((brow + pi * 16) * 128) +
                              (((uint32_t)(kk * 32) + bsel) ^ bxr);
                bhf[pi] = ldsm4(sb + OFF_BH + ro);
            }
#pragma unroll
            for (int mi = 0; mi < 4; mi++) {
#pragma unroll
                for (int ni = 0; ni < 4; ni++) {
                    const int pi = ni >> 1;
                    const bool up = ni & 1;
                    uint32_t b0 = up ? bhf[pi].z : bhf[pi].x;
                    uint32_t b1 = up ? bhf[pi].w : bhf[pi].y;
                    mma_f16(acc[mi][ni], ah[mi], b0, b1);
                }
            }
        }
        buf = (buf + 1) % 3;

        if ((g & 3) == 3) {
            const long t = z2 + (g >> 2);
            float* outr = out + t * 262144 + (long)mh * 128 * 1024 +
                          (long)nb * 128;
#pragma unroll
            for (int mi = 0; mi < 4; mi++) {
#pragma unroll
                for (int ni = 0; ni < 4; ni++) {
                    const int r0 = grow_l + mi * 16, r1 = r0 + 8;
                    const int cc = gcol_l + ni * 8;
                    stg_cs_f2(outr + (long)r0 * 1024 + cc,
                              acc[mi][ni][0] * scale, acc[mi][ni][1] * scale);
                    stg_cs_f2(outr + (long)r1 * 1024 + cc,
                              acc[mi][ni][2] * scale, acc[mi][ni][3] * scale);
                }
            }
        }
    }
}

static constexpr int SMEMB1 = 3 * 2 * TILE;  //  96 KB

// ------------------------------- launcher
extern "C" void kernel_launch(void* const* d_in, const int* in_sizes, int n_in,
                              void* d_out, int out_size)
{
    const float* batch = (const float*)d_in[0];
    const float* a_w   = (const float*)d_in[1];
    const float* a_b   = (const float*)d_in[2];
    const float* b_w   = (const float*)d_in[3];
    const float* b_b   = (const float*)d_in[4];
    const float* g_w   = (const float*)d_in[5];
    const float* g_b   = (const float*)d_in[6];
    float* out = (float*)d_out;

    void* p;
#define SYMH(v, s) cudaGetSymbolAddress(&p, s); __half* v = (__half*)p
    SYMH(batchH, g_batchH);
    SYMH(wTH, g_wTH);
    SYMH(gTH, g_gTH);
    SYMH(tpH, g_tpH);
    SYMH(attnH, g_attnH);
    SYMH(featsTH, g_featsTH);
#undef SYMH

    static bool attr_done = false;
    if (!attr_done) {
        cudaFuncSetAttribute(gemm_hmma<1, 0>,
                             cudaFuncAttributeMaxDynamicSharedMemorySize, SMEMB1);
        cudaFuncSetAttribute(gemm_hmma<2, 0>,
                             cudaFuncAttributeMaxDynamicSharedMemorySize, SMEMB1);
        cudaFuncSetAttribute(gemm_hmma<0, 0>,
                             cudaFuncAttributeMaxDynamicSharedMemorySize, SMEMB1);
        cudaFuncSetAttribute(out_kernel,
                             cudaFuncAttributeMaxDynamicSharedMemorySize, SMEMB1);
        attr_done = true;
    }

    // converts
    cvt_kernel<<<32768, 256>>>(batch, batchH, (long)67108864);
    const dim3 tb(32, 8);
    transpose_cvt_kernel<<<dim3(AA / 32, FF / 32), tb>>>(a_w, wTH, FF, AA);
    transpose_cvt_kernel<<<dim3(AA / 32, FF / 32), tb>>>(
        b_w, wTH + 256 * 1024, FF, AA);
    transpose_cvt_kernel<<<dim3(FF / 32, FF / 32), tb>>>(g_w, gTH, FF, FF);

    // tp = batch @ [a_w|b_w] + bias : M=65536, N=512, K=1024
    gemm_hmma<1, 0><<<dim3(4, 512, 1), 256, SMEMB1>>>(
        batchH, wTH, a_b, b_b, tpH, nullptr,
        512, 1024, 1024, 1024, 512, 1.0f, 0, 0, 0);

    // featsT[t][f][s]: per t, M=1024(f), N=256(s), K=1024
    gemm_hmma<2, 0><<<dim3(2, 8, 256), 256, SMEMB1>>>(
        gTH, batchH, g_b, nullptr, featsTH, nullptr,
        256, 1024, 1024, 1024, 256, 1.0f, 0, (long)256 * 1024, (long)1024 * 256);

    // attn[t] = theta[t] @ phi[t]^T : per t M=N=256, K=256
    gemm_hmma<0, 0><<<dim3(2, 2, 256), 256, SMEMB1>>>(
        tpH, tpH + 256, nullptr, nullptr, attnH, nullptr,
        256, 256, 512, 512, 256, 1.0f, 131072, 131072, 65536);

    // out[t] = (attn[t] @ feats[t]) / 512 : 2 t per CTA, .cs stores
    out_kernel<<<dim3(8, 2, 128), 256, SMEMB1>>>(
        attnH, featsTH, out, 1.0f / (float)(SS + TT));
}

// round 14
// speedup vs baseline: 1.0915x; 1.0060x over previous
#include <cuda_runtime.h>
#include <cuda_fp16.h>
#include <cstdint>

// CrossInferenceBlock via fp16 mma.sync (HMMA), all stages 1-pass.
// Graph-level concurrency: featsT runs on a forked stream concurrent with tp+attn.
//   prep -> [ tp -> attn ] (default)  ||  [ featsT ] (s2)  -> out
// GEMM: C[m][n] = sum_k A[m,k]*B[n,k], all K-major fp16.

#define TT 256
#define SS 256
#define FF 1024
#define AA 256

// ------------------------------- static scratch
__device__ __align__(16) __half g_batchH[67108864];  // [65536][1024]
__device__ __align__(16) __half g_wTH[524288];       // [512][1024] = aT|bT
__device__ __align__(16) __half g_gTH[1048576];      // g_w^T
__device__ __align__(16) __half g_tpH[33554432];     // [65536][512] theta|phi
__device__ __align__(16) __half g_attnH[16777216];   // [65536][256]
__device__ __align__(16) __half g_featsTH[67108864]; // [256][1024][256]

// ------------------------------- helpers
__device__ __forceinline__ uint32_t smem_u32(const void* p) {
    uint32_t a;
    asm("{ .reg .u64 t; cvta.to.shared.u64 t, %1; cvt.u32.u64 %0, t; }"
        : "=r"(a) : "l"(p));
    return a;
}
__device__ __forceinline__ void cpasync16(uint32_t s, const void* g) {
    asm volatile("cp.async.cg.shared.global [%0], [%1], 16;" :: "r"(s), "l"(g));
}
__device__ __forceinline__ void cp_commit() { asm volatile("cp.async.commit_group;"); }
template <int N>
__device__ __forceinline__ void cp_wait() {
    asm volatile("cp.async.wait_group %0;" :: "n"(N));
}
__device__ __forceinline__ uint4 ldsm4(uint32_t a) {
    uint4 r;
    asm volatile("ldmatrix.sync.aligned.m8n8.x4.shared.b16 {%0,%1,%2,%3}, [%4];"
                 : "=r"(r.x), "=r"(r.y), "=r"(r.z), "=r"(r.w) : "r"(a));
    return r;
}
__device__ __forceinline__ void mma_f16(float* c, const uint4& a,
                                        uint32_t b0, uint32_t b1) {
    asm volatile(
        "mma.sync.aligned.m16n8k16.row.col.f32.f16.f16.f32 "
        "{%0,%1,%2,%3},{%4,%5,%6,%7},{%8,%9},{%0,%1,%2,%3};"
        : "+f"(c[0]), "+f"(c[1]), "+f"(c[2]), "+f"(c[3])
        : "r"(a.x), "r"(a.y), "r"(a.z), "r"(a.w), "r"(b0), "r"(b1));
}
__device__ __forceinline__ void stg_cs_f2(float* p, float v0, float v1) {
    asm volatile("st.global.cs.v2.f32 [%0], {%1, %2};"
                 :: "l"(p), "f"(v0), "f"(v1) : "memory");
}

// ------------------------------- converters
__global__ void cvt_kernel(const float* __restrict__ in, __half* __restrict__ oh,
                           long n) {
    long i = ((long)blockIdx.x * blockDim.x + threadIdx.x) * 8;
    if (i >= n) return;
    float4 v0 = *(const float4*)(in + i);
    float4 v1 = *(const float4*)(in + i + 4);
    __half2 a = __floats2half2_rn(v0.x, v0.y);
    __half2 b = __floats2half2_rn(v0.z, v0.w);
    __half2 c = __floats2half2_rn(v1.x, v1.y);
    __half2 d = __floats2half2_rn(v1.z, v1.w);
    *(uint4*)(oh + i) = make_uint4(*(uint32_t*)&a, *(uint32_t*)&b,
                                   *(uint32_t*)&c, *(uint32_t*)&d);
}

__global__ void transpose_cvt_kernel(const float* __restrict__ in,
                                     __half* __restrict__ oh, int R, int C) {
    __shared__ float t[32][33];
    int c0 = blockIdx.x * 32, r0 = blockIdx.y * 32;
    int x = threadIdx.x, y = threadIdx.y;  // 32 x 8
#pragma unroll
    for (int i = 0; i < 32; i += 8)
        t[y + i][x] = in[(long)(r0 + y + i) * C + c0 + x];
    __syncthreads();
#pragma unroll
    for (int i = 0; i < 32; i += 8)
        oh[(long)(c0 + y + i) * R + r0 + x] = __float2half_rn(t[x][y + i]);
}

// ------------------------------- GEMM: BM=128 BN=128 BK=64, 3-stage cp.async
static constexpr int TILE = 16384;  // 128 x 64 fp16
static constexpr int OFF_AH = 0;
static constexpr int OFF_BH = TILE;

// BMODE: 0 none, 1 col-bias (bias n<256 / bias2 n>=256), 2 row-bias (bias[m])
// OUTM : 0 = fp16, 2 = fp32
template <int BMODE, int OUTM>
__global__ void __launch_bounds__(256, 2) gemm_hmma(
    const __half* __restrict__ Ah, const __half* __restrict__ Bh,
    const float* __restrict__ bias, const float* __restrict__ bias2,
    __half* __restrict__ Ch, float* __restrict__ Cf,
    int N, int K, int lda, int ldb, int ldc, float scale,
    long sA, long sB, long sC)
{
    constexpr int STAGE = 2 * TILE;
    extern __shared__ __align__(1024) char smem[];
    const uint32_t sbase = smem_u32(smem);
    const int tid = threadIdx.x;
    const int wid = tid >> 5, lane = tid & 31;
    const long z = blockIdx.z;
    const int block_row = blockIdx.y * 128;
    const int block_col = blockIdx.x * 128;

    const __half* Az_h = Ah + z * sA + (long)block_row * lda;
    const __half* Bz_h = Bh + z * sB + (long)block_col * ldb;

    int c_row[4]; int c_co[4]; uint32_t c_so[4];
#pragma unroll
    for (int i = 0; i < 4; i++) {
        int q = tid + i * 256;
        int r = q >> 3, u = q & 7;
        c_row[i] = r;
        c_co[i] = u * 8;
        c_so[i] = (uint32_t)(r * 128 + ((u ^ (r & 7)) << 4));
    }

    auto load_stage = [&](int buf, int k0) {
        uint32_t sb = sbase + buf * STAGE;
#pragma unroll
        for (int i = 0; i < 4; i++) {
            long ga = (long)c_row[i] * lda + k0 + c_co[i];
            long gb = (long)c_row[i] * ldb + k0 + c_co[i];
            cpasync16(sb + OFF_AH + c_so[i], Az_h + ga);
            cpasync16(sb + OFF_BH + c_so[i], Bz_h + gb);
        }
    };

    const int wm = wid & 1, wn = wid >> 1;
    const int arow = wm * 64 + (lane & 15);
    const uint32_t asel = ((lane >> 4) & 1) * 16;
    const uint32_t axr = (uint32_t)((arow & 7) << 4);
    const int brow = wn * 32 + (lane & 7) + ((lane & 16) ? 8 : 0);
    const uint32_t bsel = (lane & 8) ? 16u : 0u;
    const uint32_t bxr = (uint32_t)((brow & 7) << 4);

    float acc[4][4][4];
#pragma unroll
    for (int a = 0; a < 4; a++)
#pragma unroll
        for (int b = 0; b < 4; b++)
#pragma unroll
            for (int c = 0; c < 4; c++) acc[a][b][c] = 0.0f;

    const int NT = K >> 6;
    load_stage(0, 0);
    cp_commit();
    if (NT > 1) load_stage(1, 64);
    cp_commit();

    int buf = 0;
    for (int it = 0; it < NT; it++) {
        cp_wait<1>();
        __syncthreads();
        if (it + 2 < NT) load_stage((it + 2) % 3, (it + 2) << 6);
        cp_commit();

        const uint32_t sb = sbase + buf * STAGE;
#pragma unroll
        for (int kk = 0; kk < 4; kk++) {
            uint4 ah[4], bhf[2];
#pragma unroll
            for (int mi = 0; mi < 4; mi++) {
                uint32_t ro = (uint32_t)((arow + mi * 16) * 128) +
                              (((uint32_t)(kk * 32) + asel) ^ axr);
                ah[mi] = ldsm4(sb + OFF_AH + ro);
            }
#pragma unroll
            for (int pi = 0; pi < 2; pi++) {
                uint32_t ro = (uint32_t)((brow + pi * 16) * 128) +
                              (((uint32_t)(kk * 32) + bsel) ^ bxr);
                bhf[pi] = ldsm4(sb + OFF_BH + ro);
            }
#pragma unroll
            for (int mi = 0; mi < 4; mi++) {
#pragma unroll
                for (int ni = 0; ni < 4; ni++) {
                    const int pi = ni >> 1;
                    const bool up = ni & 1;
                    uint32_t bh0 = up ? bhf[pi].z : bhf[pi].x;
                    uint32_t bh1 = up ? bhf[pi].w : bhf[pi].y;
                    mma_f16(acc[mi][ni], ah[mi], bh0, bh1);
                }
            }
        }
        buf = (buf + 1) % 3;
    }

    const int grow0 = block_row + wm * 64 + (lane >> 2);
    const int gcol0 = block_col + wn * 32 + (lane & 3) * 2;
#pragma unroll
    for (int mi = 0; mi < 4; mi++) {
#pragma unroll
        for (int ni = 0; ni < 4; ni++) {
            float v0 = acc[mi][ni][0], v1 = acc[mi][ni][1];
            float v2 = acc[mi][ni][2], v3 = acc[mi][ni][3];
            const int r0 = grow0 + mi * 16, r1 = r0 + 8;
            const int cc = gcol0 + ni * 8;
            if (BMODE == 1) {
                float b0 = (cc < 256) ? bias[cc] : bias2[cc - 256];
                float b1 = (cc + 1 < 256) ? bias[cc + 1] : bias2[cc + 1 - 256];
                v0 += b0; v1 += b1; v2 += b0; v3 += b1;
            }
            if (BMODE == 2) {
                float ba = bias[r0], bb = bias[r1];
                v0 += ba; v1 += ba; v2 += bb; v3 += bb;
            }
            v0 *= scale; v1 *= scale; v2 *= scale; v3 *= scale;
            const long o0 = z * sC + (long)r0 * ldc + cc;
            const long o1 = z * sC + (long)r1 * ldc + cc;
            if (OUTM == 0) {
                __half2 p0 = __floats2half2_rn(v0, v1);
                __half2 p1 = __floats2half2_rn(v2, v3);
                *(uint32_t*)(Ch + o0) = *(uint32_t*)&p0;
                *(uint32_t*)(Ch + o1) = *(uint32_t*)&p1;
            } else {
                *(float2*)(Cf + o0) = make_float2(v0, v1);
                *(float2*)(Cf + o1) = make_float2(v2, v3);
            }
        }
    }
}

// ------------------------------- out kernel: 2 t-values per CTA, continuous pipe
__global__ void __launch_bounds__(256, 2) out_kernel(
    const __half* __restrict__ attnH, const __half* __restrict__ featsTH,
    float* __restrict__ out, float scale)
{
    extern __shared__ __align__(1024) char smem[];
    const uint32_t sbase = smem_u32(smem);
    const int tid = threadIdx.x;
    const int wid = tid >> 5, lane = tid & 31;
    const int nb = blockIdx.x, mh = blockIdx.y;
    const long z2 = (long)blockIdx.z * 2;

    int c_row[4]; int c_co[4]; uint32_t c_so[4];
#pragma unroll
    for (int i = 0; i < 4; i++) {
        int q = tid + i * 256;
        int r = q >> 3, u = q & 7;
        c_row[i] = r;
        c_co[i] = u * 8;
        c_so[i] = (uint32_t)(r * 128 + ((u ^ (r & 7)) << 4));
    }

    auto loadg = [&](int buf, int g) {   // g = ti*4 + kt
        uint32_t sb = sbase + buf * 2 * TILE;
        const long t = z2 + (g >> 2);
        const int kt = g & 3;
        const __half* Aa = attnH + (t * 256 + mh * 128) * 256;
        const __half* Bf = featsTH + t * 262144 + (long)nb * 128 * 256;
#pragma unroll
        for (int i = 0; i < 4; i++) {
            long ga = (long)c_row[i] * 256 + kt * 64 + c_co[i];
            cpasync16(sb + OFF_AH + c_so[i], Aa + ga);
            cpasync16(sb + OFF_BH + c_so[i], Bf + ga);
        }
    };

    const int wm = wid & 1, wn = wid >> 1;
    const int arow = wm * 64 + (lane & 15);
    const uint32_t asel = ((lane >> 4) & 1) * 16;
    const uint32_t axr = (uint32_t)((arow & 7) << 4);
    const int brow = wn * 32 + (lane & 7) + ((lane & 16) ? 8 : 0);
    const uint32_t bsel = (lane & 8) ? 16u : 0u;
    const uint32_t bxr = (uint32_t)((brow & 7) << 4);
    const int grow_l = wm * 64 + (lane >> 2);
    const int gcol_l = wn * 32 + (lane & 3) * 2;

    float acc[4][4][4];

    loadg(0, 0);
    cp_commit();
    loadg(1, 1);
    cp_commit();

    int buf = 0;
    for (int g = 0; g < 8; g++) {
        if ((g & 3) == 0) {
#pragma unroll
            for (int a = 0; a < 4; a++)
#pragma unroll
                for (int b = 0; b < 4; b++)
#pragma unroll
                    for (int c = 0; c < 4; c++) acc[a][b][c] = 0.0f;
        }
        cp_wait<1>();
        __syncthreads();
        if (g + 2 < 8) loadg((g + 2) % 3, g + 2);
        cp_commit();

        const uint32_t sb = sbase + buf * 2 * TILE;
#pragma unroll
        for (int kk = 0; kk < 4; kk++) {
            uint4 ah[4], bhf[2];
#pragma unroll
            for (int mi = 0; mi < 4; mi++) {
                uint32_t ro = (uint32_t)((arow + mi * 16) * 128) +
                              (((uint32_t)(kk * 32) + asel) ^ axr);
                ah[mi] = ldsm4(sb + OFF_AH + ro);
            }
#pragma unroll
            for (int pi = 0; pi < 2; pi++) {
                uint32_t ro = (uint32_t)((brow + pi * 16) * 128) +
                              (((uint32_t)(kk * 32) + bsel) ^ bxr);
                bhf[pi] = ldsm4(sb + OFF_BH + ro);
            }
#pragma unroll
            for (int mi = 0; mi < 4; mi++) {
#pragma unroll
                for (int ni = 0; ni < 4; ni++) {
                    const int pi = ni >> 1;
                    const bool up = ni & 1;
                    uint32_t b0 = up ? bhf[pi].z : bhf[pi].x;
                    uint32_t b1 = up ? bhf[pi].w : bhf[pi].y;
                    mma_f16(acc[mi][ni], ah[mi], b0, b1);
                }
            }
        }
        buf = (buf + 1) % 3;

        if ((g & 3) == 3) {
            const long t = z2 + (g >> 2);
            float* outr = out + t * 262144 + (long)mh * 128 * 1024 +
                          (long)nb * 128;
#pragma unroll
            for (int mi = 0; mi < 4; mi++) {
#pragma unroll
                for (int ni = 0; ni < 4; ni++) {
                    const int r0 = grow_l + mi * 16, r1 = r0 + 8;
                    const int cc = gcol_l + ni * 8;
                    stg_cs_f2(outr + (long)r0 * 1024 + cc,
                              acc[mi][ni][0] * scale, acc[mi][ni][1] * scale);
                    stg_cs_f2(outr + (long)r1 * 1024 + cc,
                              acc[mi][ni][2] * scale, acc[mi][ni][3] * scale);
                }
            }
        }
    }
}

static constexpr int SMEMB1 = 3 * 2 * TILE;  //  96 KB

// ------------------------------- launcher
extern "C" void kernel_launch(void* const* d_in, const int* in_sizes, int n_in,
                              void* d_out, int out_size)
{
    const float* batch = (const float*)d_in[0];
    const float* a_w   = (const float*)d_in[1];
    const float* a_b   = (const float*)d_in[2];
    const float* b_w   = (const float*)d_in[3];
    const float* b_b   = (const float*)d_in[4];
    const float* g_w   = (const float*)d_in[5];
    const float* g_b   = (const float*)d_in[6];
    float* out = (float*)d_out;

    void* p;
#define SYMH(v, s) cudaGetSymbolAddress(&p, s); __half* v = (__half*)p
    SYMH(batchH, g_batchH);
    SYMH(wTH, g_wTH);
    SYMH(gTH, g_gTH);
    SYMH(tpH, g_tpH);
    SYMH(attnH, g_attnH);
    SYMH(featsTH, g_featsTH);
#undef SYMH

    // one-time setup (runs during the uncaptured correctness call)
    static cudaStream_t s2 = nullptr;
    static cudaEvent_t evPrep = nullptr, evFeats = nullptr;
    static bool init_done = false;
    if (!init_done) {
        cudaFuncSetAttribute(gemm_hmma<1, 0>,
                             cudaFuncAttributeMaxDynamicSharedMemorySize, SMEMB1);
        cudaFuncSetAttribute(gemm_hmma<2, 0>,
                             cudaFuncAttributeMaxDynamicSharedMemorySize, SMEMB1);
        cudaFuncSetAttribute(gemm_hmma<0, 0>,
                             cudaFuncAttributeMaxDynamicSharedMemorySize, SMEMB1);
        cudaFuncSetAttribute(out_kernel,
                             cudaFuncAttributeMaxDynamicSharedMemorySize, SMEMB1);
        cudaStreamCreateWithFlags(&s2, cudaStreamNonBlocking);
        cudaEventCreateWithFlags(&evPrep, cudaEventDisableTiming);
        cudaEventCreateWithFlags(&evFeats, cudaEventDisableTiming);
        init_done = true;
    }

    // ---- prep (default stream) ----
    cvt_kernel<<<32768, 256>>>(batch, batchH, (long)67108864);
    const dim3 tb(32, 8);
    transpose_cvt_kernel<<<dim3(AA / 32, FF / 32), tb>>>(a_w, wTH, FF, AA);
    transpose_cvt_kernel<<<dim3(AA / 32, FF / 32), tb>>>(
        b_w, wTH + 256 * 1024, FF, AA);
    transpose_cvt_kernel<<<dim3(FF / 32, FF / 32), tb>>>(g_w, gTH, FF, FF);
    cudaEventRecord(evPrep, 0);

    // ---- fork: featsT on s2 (depends only on prep) ----
    cudaStreamWaitEvent(s2, evPrep, 0);
    gemm_hmma<2, 0><<<dim3(2, 8, 256), 256, SMEMB1, s2>>>(
        gTH, batchH, g_b, nullptr, featsTH, nullptr,
        256, 1024, 1024, 1024, 256, 1.0f, 0, (long)256 * 1024, (long)1024 * 256);
    cudaEventRecord(evFeats, s2);

    // ---- default stream: tp -> attn ----
    gemm_hmma<1, 0><<<dim3(4, 512, 1), 256, SMEMB1>>>(
        batchH, wTH, a_b, b_b, tpH, nullptr,
        512, 1024, 1024, 1024, 512, 1.0f, 0, 0, 0);

    gemm_hmma<0, 0><<<dim3(2, 2, 256), 256, SMEMB1>>>(
        tpH, tpH + 256, nullptr, nullptr, attnH, nullptr,
        256, 256, 512, 512, 256, 1.0f, 131072, 131072, 65536);

    // ---- join: out needs attn (default) + featsT (s2) ----
    cudaStreamWaitEvent(0, evFeats, 0);
    out_kernel<<<dim3(8, 2, 128), 256, SMEMB1>>>(
        attnH, featsTH, out, 1.0f / (float)(SS + TT));
}

// round 15
// speedup vs baseline: 1.1073x; 1.0145x over previous
#include <cuda_runtime.h>
#include <cuda_fp16.h>
#include <cstdint>

// CrossInferenceBlock via fp16 mma.sync (HMMA), all stages 1-pass.
// t-halved software pipeline across streams:
//   prep -> s2: feats_h0, feats_h1 ; s1: tp, attn_h0, attn_h1
//   s3: out_h0 (after attn_h0+feats_h0, overlaps h1 compute) ; s1: out_h1
// GEMM: C[m][n] = sum_k A[m,k]*B[n,k], all K-major fp16.

#define TT 256
#define SS 256
#define FF 1024
#define AA 256

// ------------------------------- static scratch
__device__ __align__(16) __half g_batchH[67108864];  // [65536][1024]
__device__ __align__(16) __half g_wTH[524288];       // [512][1024] = aT|bT
__device__ __align__(16) __half g_gTH[1048576];      // g_w^T
__device__ __align__(16) __half g_tpH[33554432];     // [65536][512] theta|phi
__device__ __align__(16) __half g_attnH[16777216];   // [65536][256]
__device__ __align__(16) __half g_featsTH[67108864]; // [256][1024][256]

// ------------------------------- helpers
__device__ __forceinline__ uint32_t smem_u32(const void* p) {
    uint32_t a;
    asm("{ .reg .u64 t; cvta.to.shared.u64 t, %1; cvt.u32.u64 %0, t; }"
        : "=r"(a) : "l"(p));
    return a;
}
__device__ __forceinline__ void cpasync16(uint32_t s, const void* g) {
    asm volatile("cp.async.cg.shared.global [%0], [%1], 16;" :: "r"(s), "l"(g));
}
__device__ __forceinline__ void cp_commit() { asm volatile("cp.async.commit_group;"); }
template <int N>
__device__ __forceinline__ void cp_wait() {
    asm volatile("cp.async.wait_group %0;" :: "n"(N));
}
__device__ __forceinline__ uint4 ldsm4(uint32_t a) {
    uint4 r;
    asm volatile("ldmatrix.sync.aligned.m8n8.x4.shared.b16 {%0,%1,%2,%3}, [%4];"
                 : "=r"(r.x), "=r"(r.y), "=r"(r.z), "=r"(r.w) : "r"(a));
    return r;
}
__device__ __forceinline__ void mma_f16(float* c, const uint4& a,
                                        uint32_t b0, uint32_t b1) {
    asm volatile(
        "mma.sync.aligned.m16n8k16.row.col.f32.f16.f16.f32 "
        "{%0,%1,%2,%3},{%4,%5,%6,%7},{%8,%9},{%0,%1,%2,%3};"
        : "+f"(c[0]), "+f"(c[1]), "+f"(c[2]), "+f"(c[3])
        : "r"(a.x), "r"(a.y), "r"(a.z), "r"(a.w), "r"(b0), "r"(b1));
}
__device__ __forceinline__ void stg_cs_f2(float* p, float v0, float v1) {
    asm volatile("st.global.cs.v2.f32 [%0], {%1, %2};"
                 :: "l"(p), "f"(v0), "f"(v1) : "memory");
}

// ------------------------------- converters
__global__ void cvt_kernel(const float* __restrict__ in, __half* __restrict__ oh,
                           long n) {
    long i = ((long)blockIdx.x * blockDim.x + threadIdx.x) * 8;
    if (i >= n) return;
    float4 v0 = *(const float4*)(in + i);
    float4 v1 = *(const float4*)(in + i + 4);
    __half2 a = __floats2half2_rn(v0.x, v0.y);
    __half2 b = __floats2half2_rn(v0.z, v0.w);
    __half2 c = __floats2half2_rn(v1.x, v1.y);
    __half2 d = __floats2half2_rn(v1.z, v1.w);
    *(uint4*)(oh + i) = make_uint4(*(uint32_t*)&a, *(uint32_t*)&b,
                                   *(uint32_t*)&c, *(uint32_t*)&d);
}

__global__ void transpose_cvt_kernel(const float* __restrict__ in,
                                     __half* __restrict__ oh, int R, int C) {
    __shared__ float t[32][33];
    int c0 = blockIdx.x * 32, r0 = blockIdx.y * 32;
    int x = threadIdx.x, y = threadIdx.y;  // 32 x 8
#pragma unroll
    for (int i = 0; i < 32; i += 8)
        t[y + i][x] = in[(long)(r0 + y + i) * C + c0 + x];
    __syncthreads();
#pragma unroll
    for (int i = 0; i < 32; i += 8)
        oh[(long)(c0 + y + i) * R + r0 + x] = __float2half_rn(t[x][y + i]);
}

// ------------------------------- GEMM: BM=128 BN=128 BK=64, 3-stage cp.async
static constexpr int TILE = 16384;  // 128 x 64 fp16
static constexpr int OFF_AH = 0;
static constexpr int OFF_BH = TILE;

// BMODE: 0 none, 1 col-bias (bias n<256 / bias2 n>=256), 2 row-bias (bias[m])
// OUTM : 0 = fp16, 2 = fp32
template <int BMODE, int OUTM>
__global__ void __launch_bounds__(256, 2) gemm_hmma(
    const __half* __restrict__ Ah, const __half* __restrict__ Bh,
    const float* __restrict__ bias, const float* __restrict__ bias2,
    __half* __restrict__ Ch, float* __restrict__ Cf,
    int N, int K, int lda, int ldb, int ldc, float scale,
    long sA, long sB, long sC)
{
    constexpr int STAGE = 2 * TILE;
    extern __shared__ __align__(1024) char smem[];
    const uint32_t sbase = smem_u32(smem);
    const int tid = threadIdx.x;
    const int wid = tid >> 5, lane = tid & 31;
    const long z = blockIdx.z;
    const int block_row = blockIdx.y * 128;
    const int block_col = blockIdx.x * 128;

    const __half* Az_h = Ah + z * sA + (long)block_row * lda;
    const __half* Bz_h = Bh + z * sB + (long)block_col * ldb;

    int c_row[4]; int c_co[4]; uint32_t c_so[4];
#pragma unroll
    for (int i = 0; i < 4; i++) {
        int q = tid + i * 256;
        int r = q >> 3, u = q & 7;
        c_row[i] = r;
        c_co[i] = u * 8;
        c_so[i] = (uint32_t)(r * 128 + ((u ^ (r & 7)) << 4));
    }

    auto load_stage = [&](int buf, int k0) {
        uint32_t sb = sbase + buf * STAGE;
#pragma unroll
        for (int i = 0; i < 4; i++) {
            long ga = (long)c_row[i] * lda + k0 + c_co[i];
            long gb = (long)c_row[i] * ldb + k0 + c_co[i];
            cpasync16(sb + OFF_AH + c_so[i], Az_h + ga);
            cpasync16(sb + OFF_BH + c_so[i], Bz_h + gb);
        }
    };

    const int wm = wid & 1, wn = wid >> 1;
    const int arow = wm * 64 + (lane & 15);
    const uint32_t asel = ((lane >> 4) & 1) * 16;
    const uint32_t axr = (uint32_t)((arow & 7) << 4);
    const int brow = wn * 32 + (lane & 7) + ((lane & 16) ? 8 : 0);
    const uint32_t bsel = (lane & 8) ? 16u : 0u;
    const uint32_t bxr = (uint32_t)((brow & 7) << 4);

    float acc[4][4][4];
#pragma unroll
    for (int a = 0; a < 4; a++)
#pragma unroll
        for (int b = 0; b < 4; b++)
#pragma unroll
            for (int c = 0; c < 4; c++) acc[a][b][c] = 0.0f;

    const int NT = K >> 6;
    load_stage(0, 0);
    cp_commit();
    if (NT > 1) load_stage(1, 64);
    cp_commit();

    int buf = 0;
    for (int it = 0; it < NT; it++) {
        cp_wait<1>();
        __syncthreads();
        if (it + 2 < NT) load_stage((it + 2) % 3, (it + 2) << 6);
        cp_commit();

        const uint32_t sb = sbase + buf * STAGE;
#pragma unroll
        for (int kk = 0; kk < 4; kk++) {
            uint4 ah[4], bhf[2];
#pragma unroll
            for (int mi = 0; mi < 4; mi++) {
                uint32_t ro = (uint32_t)((arow + mi * 16) * 128) +
                              (((uint32_t)(kk * 32) + asel) ^ axr);
                ah[mi] = ldsm4(sb + OFF_AH + ro);
            }
#pragma unroll
            for (int pi = 0; pi < 2; pi++) {
                uint32_t ro = (uint32_t)((brow + pi * 16) * 128) +
                              (((uint32_t)(kk * 32) + bsel) ^ bxr);
                bhf[pi] = ldsm4(sb + OFF_BH + ro);
            }
#pragma unroll
            for (int mi = 0; mi < 4; mi++) {
#pragma unroll
                for (int ni = 0; ni < 4; ni++) {
                    const int pi = ni >> 1;
                    const bool up = ni & 1;
                    uint32_t bh0 = up ? bhf[pi].z : bhf[pi].x;
                    uint32_t bh1 = up ? bhf[pi].w : bhf[pi].y;
                    mma_f16(acc[mi][ni], ah[mi], bh0, bh1);
                }
            }
        }
        buf = (buf + 1) % 3;
    }

    const int grow0 = block_row + wm * 64 + (lane >> 2);
    const int gcol0 = block_col + wn * 32 + (lane & 3) * 2;
#pragma unroll
    for (int mi = 0; mi < 4; mi++) {
#pragma unroll
        for (int ni = 0; ni < 4; ni++) {
            float v0 = acc[mi][ni][0], v1 = acc[mi][ni][1];
            float v2 = acc[mi][ni][2], v3 = acc[mi][ni][3];
            const int r0 = grow0 + mi * 16, r1 = r0 + 8;
            const int cc = gcol0 + ni * 8;
            if (BMODE == 1) {
                float b0 = (cc < 256) ? bias[cc] : bias2[cc - 256];
                float b1 = (cc + 1 < 256) ? bias[cc + 1] : bias2[cc + 1 - 256];
                v0 += b0; v1 += b1; v2 += b0; v3 += b1;
            }
            if (BMODE == 2) {
                float ba = bias[r0], bb = bias[r1];
                v0 += ba; v1 += ba; v2 += bb; v3 += bb;
            }
            v0 *= scale; v1 *= scale; v2 *= scale; v3 *= scale;
            const long o0 = z * sC + (long)r0 * ldc + cc;
            const long o1 = z * sC + (long)r1 * ldc + cc;
            if (OUTM == 0) {
                __half2 p0 = __floats2half2_rn(v0, v1);
                __half2 p1 = __floats2half2_rn(v2, v3);
                *(uint32_t*)(Ch + o0) = *(uint32_t*)&p0;
                *(uint32_t*)(Ch + o1) = *(uint32_t*)&p1;
            } else {
                *(float2*)(Cf + o0) = make_float2(v0, v1);
                *(float2*)(Cf + o1) = make_float2(v2, v3);
            }
        }
    }
}

// ------------------------------- out kernel: 2 t-values per CTA, continuous pipe
__global__ void __launch_bounds__(256, 2) out_kernel(
    const __half* __restrict__ attnH, const __half* __restrict__ featsTH,
    float* __restrict__ out, float scale)
{
    extern __shared__ __align__(1024) char smem[];
    const uint32_t sbase = smem_u32(smem);
    const int tid = threadIdx.x;
    const int wid = tid >> 5, lane = tid & 31;
    const int nb = blockIdx.x, mh = blockIdx.y;
    const long z2 = (long)blockIdx.z * 2;

    int c_row[4]; int c_co[4]; uint32_t c_so[4];
#pragma unroll
    for (int i = 0; i < 4; i++) {
        int q = tid + i * 256;
        int r = q >> 3, u = q & 7;
        c_row[i] = r;
        c_co[i] = u * 8;
        c_so[i] = (uint32_t)(r * 128 + ((u ^ (r & 7)) << 4));
    }

    auto loadg = [&](int buf, int g) {   // g = ti*4 + kt
        uint32_t sb = sbase + buf * 2 * TILE;
        const long t = z2 + (g >> 2);
        const int kt = g & 3;
        const __half* Aa = attnH + (t * 256 + mh * 128) * 256;
        const __half* Bf = featsTH + t * 262144 + (long)nb * 128 * 256;
#pragma unroll
        for (int i = 0; i < 4; i++) {
            long ga = (long)c_row[i] * 256 + kt * 64 + c_co[i];
            cpasync16(sb + OFF_AH + c_so[i], Aa + ga);
            cpasync16(sb + OFF_BH + c_so[i], Bf + ga);
        }
    };

    const int wm = wid & 1, wn = wid >> 1;
    const int arow = wm * 64 + (lane & 15);
    const uint32_t asel = ((lane >> 4) & 1) * 16;
    const uint32_t axr = (uint32_t)((arow & 7) << 4);
    const int brow = wn * 32 + (lane & 7) + ((lane & 16) ? 8 : 0);
    const uint32_t bsel = (lane & 8) ? 16u : 0u;
    const uint32_t bxr = (uint32_t)((brow & 7) << 4);
    const int grow_l = wm * 64 + (lane >> 2);
    const int gcol_l = wn * 32 + (lane & 3) * 2;

    float acc[4][4][4];

    loadg(0, 0);
    cp_commit();
    loadg(1, 1);
    cp_commit();

    int buf = 0;
    for (int g = 0; g < 8; g++) {
        if ((g & 3) == 0) {
#pragma unroll
            for (int a = 0; a < 4; a++)
#pragma unroll
                for (int b = 0; b < 4; b++)
#pragma unroll
                    for (int c = 0; c < 4; c++) acc[a][b][c] = 0.0f;
        }
        cp_wait<1>();
        __syncthreads();
        if (g + 2 < 8) loadg((g + 2) % 3, g + 2);
        cp_commit();

        const uint32_t sb = sbase + buf * 2 * TILE;
#pragma unroll
        for (int kk = 0; kk < 4; kk++) {
            uint4 ah[4], bhf[2];
#pragma unroll
            for (int mi = 0; mi < 4; mi++) {
                uint32_t ro = (uint32_t)((arow + mi * 16) * 128) +
                              (((uint32_t)(kk * 32) + asel) ^ axr);
                ah[mi] = ldsm4(sb + OFF_AH + ro);
            }
#pragma unroll
            for (int pi = 0; pi < 2; pi++) {
                uint32_t ro = (uint32_t)((brow + pi * 16) * 128) +
                              (((uint32_t)(kk * 32) + bsel) ^ bxr);
                bhf[pi] = ldsm4(sb + OFF_BH + ro);
            }
#pragma unroll
            for (int mi = 0; mi < 4; mi++) {
#pragma unroll
                for (int ni = 0; ni < 4; ni++) {
                    const int pi = ni >> 1;
                    const bool up = ni & 1;
                    uint32_t b0 = up ? bhf[pi].z : bhf[pi].x;
                    uint32_t b1 = up ? bhf[pi].w : bhf[pi].y;
                    mma_f16(acc[mi][ni], ah[mi], b0, b1);
                }
            }
        }
        buf = (buf + 1) % 3;

        if ((g & 3) == 3) {
            const long t = z2 + (g >> 2);
            float* outr = out + t * 262144 + (long)mh * 128 * 1024 +
                          (long)nb * 128;
#pragma unroll
            for (int mi = 0; mi < 4; mi++) {
#pragma unroll
                for (int ni = 0; ni < 4; ni++) {
                    const int r0 = grow_l + mi * 16, r1 = r0 + 8;
                    const int cc = gcol_l + ni * 8;
                    stg_cs_f2(outr + (long)r0 * 1024 + cc,
                              acc[mi][ni][0] * scale, acc[mi][ni][1] * scale);
                    stg_cs_f2(outr + (long)r1 * 1024 + cc,
                              acc[mi][ni][2] * scale, acc[mi][ni][3] * scale);
                }
            }
        }
    }
}

static constexpr int SMEMB1 = 3 * 2 * TILE;  //  96 KB

// ------------------------------- launcher
extern "C" void kernel_launch(void* const* d_in, const int* in_sizes, int n_in,
                              void* d_out, int out_size)
{
    const float* batch = (const float*)d_in[0];
    const float* a_w   = (const float*)d_in[1];
    const float* a_b   = (const float*)d_in[2];
    const float* b_w   = (const float*)d_in[3];
    const float* b_b   = (const float*)d_in[4];
    const float* g_w   = (const float*)d_in[5];
    const float* g_b   = (const float*)d_in[6];
    float* out = (float*)d_out;

    void* p;
#define SYMH(v, s) cudaGetSymbolAddress(&p, s); __half* v = (__half*)p
    SYMH(batchH, g_batchH);
    SYMH(wTH, g_wTH);
    SYMH(gTH, g_gTH);
    SYMH(tpH, g_tpH);
    SYMH(attnH, g_attnH);
    SYMH(featsTH, g_featsTH);
#undef SYMH

    static cudaStream_t s2 = nullptr, s3 = nullptr;
    static cudaEvent_t evPrep = nullptr, evF0 = nullptr, evF1 = nullptr,
                       evA0 = nullptr, evO0 = nullptr;
    static bool init_done = false;
    if (!init_done) {
        cudaFuncSetAttribute(gemm_hmma<1, 0>,
                             cudaFuncAttributeMaxDynamicSharedMemorySize, SMEMB1);
        cudaFuncSetAttribute(gemm_hmma<2, 0>,
                             cudaFuncAttributeMaxDynamicSharedMemorySize, SMEMB1);
        cudaFuncSetAttribute(gemm_hmma<0, 0>,
                             cudaFuncAttributeMaxDynamicSharedMemorySize, SMEMB1);
        cudaFuncSetAttribute(out_kernel,
                             cudaFuncAttributeMaxDynamicSharedMemorySize, SMEMB1);
        cudaStreamCreateWithFlags(&s2, cudaStreamNonBlocking);
        cudaStreamCreateWithFlags(&s3, cudaStreamNonBlocking);
        cudaEventCreateWithFlags(&evPrep, cudaEventDisableTiming);
        cudaEventCreateWithFlags(&evF0, cudaEventDisableTiming);
        cudaEventCreateWithFlags(&evF1, cudaEventDisableTiming);
        cudaEventCreateWithFlags(&evA0, cudaEventDisableTiming);
        cudaEventCreateWithFlags(&evO0, cudaEventDisableTiming);
        init_done = true;
    }

    const float oscale = 1.0f / (float)(SS + TT);
    const long HT = 128;                       // t-half size
    const long tpStrT    = 131072;             // tp elems per t (512*256)
    const long attnStrT  = 65536;              // attn elems per t
    const long featStrT  = 262144;             // featsT elems per t
    const long outStrT   = 262144;             // out elems per t

    // ---- prep (default stream) ----
    cvt_kernel<<<32768, 256>>>(batch, batchH, (long)67108864);
    const dim3 tb(32, 8);
    transpose_cvt_kernel<<<dim3(AA / 32, FF / 32), tb>>>(a_w, wTH, FF, AA);
    transpose_cvt_kernel<<<dim3(AA / 32, FF / 32), tb>>>(
        b_w, wTH + 256 * 1024, FF, AA);
    transpose_cvt_kernel<<<dim3(FF / 32, FF / 32), tb>>>(g_w, gTH, FF, FF);
    cudaEventRecord(evPrep, 0);

    // ---- s2: featsT half 0, then half 1 ----
    cudaStreamWaitEvent(s2, evPrep, 0);
    gemm_hmma<2, 0><<<dim3(2, 8, 128), 256, SMEMB1, s2>>>(
        gTH, batchH, g_b, nullptr, featsTH, nullptr,
        256, 1024, 1024, 1024, 256, 1.0f, 0, (long)256 * 1024, featStrT);
    cudaEventRecord(evF0, s2);
    gemm_hmma<2, 0><<<dim3(2, 8, 128), 256, SMEMB1, s2>>>(
        gTH, batchH + HT * featStrT, g_b, nullptr,
        featsTH + HT * featStrT, nullptr,
        256, 1024, 1024, 1024, 256, 1.0f, 0, (long)256 * 1024, featStrT);
    cudaEventRecord(evF1, s2);

    // ---- default: tp -> attn halves ----
    gemm_hmma<1, 0><<<dim3(4, 512, 1), 256, SMEMB1>>>(
        batchH, wTH, a_b, b_b, tpH, nullptr,
        512, 1024, 1024, 1024, 512, 1.0f, 0, 0, 0);

    gemm_hmma<0, 0><<<dim3(2, 2, 128), 256, SMEMB1>>>(
        tpH, tpH + 256, nullptr, nullptr, attnH, nullptr,
        256, 256, 512, 512, 256, 1.0f, tpStrT, tpStrT, attnStrT);
    cudaEventRecord(evA0, 0);
    gemm_hmma<0, 0><<<dim3(2, 2, 128), 256, SMEMB1>>>(
        tpH + HT * tpStrT, tpH + HT * tpStrT + 256, nullptr, nullptr,
        attnH + HT * attnStrT, nullptr,
        256, 256, 512, 512, 256, 1.0f, tpStrT, tpStrT, attnStrT);

    // ---- s3: out half 0 (overlaps h1 compute) ----
    cudaStreamWaitEvent(s3, evA0, 0);
    cudaStreamWaitEvent(s3, evF0, 0);
    out_kernel<<<dim3(8, 2, 64), 256, SMEMB1, s3>>>(
        attnH, featsTH, out, oscale);
    cudaEventRecord(evO0, s3);

    // ---- default: out half 1, then join s3 ----
    cudaStreamWaitEvent(0, evF1, 0);
    out_kernel<<<dim3(8, 2, 64), 256, SMEMB1>>>(
        attnH + HT * attnStrT, featsTH + HT * featStrT,
        out + HT * outStrT, oscale);
    cudaStreamWaitEvent(0, evO0, 0);
}